// round 8
// baseline (speedup 1.0000x reference)
#include <cuda_runtime.h>
#include <cuda_bf16.h>

// Blockwise 256-point regular Hadamard transform (H = kron(H4 x4) / 16).
// Fast transform, 4 radix-4 stages acting on independent base-4 digits
// (stages commute -> single smem transpose suffices).
//
//   1. 4x LDG.128: thread (h,j) loads elements e = 16j + i of block h
//   2. butterfly digits d0,d1 in registers
//   3. one smem transpose (scalar STS cols, LDS.128 rows; RS=20/SB=336
//      geometry is bank-conflict-free in both phases)
//   4. thread holds e = 16k + j; butterfly digits d2,d3 in registers
//   5. R7: shuffle-paired STG.64 stores. Lanes j<->j^1 exchange via
//      shfl_xor; even lanes store even-k pairs, odd lanes odd-k pairs.
//      Per store instruction each 16-lane block writes ONE dense 128B
//      line (even lanes bytes [128m,128m+64), odd lanes [+64,+128)).
//      Store wavefronts: 32 -> 16 per warp (L1 was the top unit at 80%).
//
// Final 1/16 scale folded into the last stage.

#define BF4(a,b,c,d)                                   \
    do {                                               \
        float _s = ((a)+(b)) + ((c)+(d));              \
        float _ta=(a), _tb=(b), _tc=(c);               \
        (a) = fmaf(-2.0f, (d), _s);                    \
        (b) = fmaf(-2.0f, _tc, _s);                    \
        (c) = fmaf(-2.0f, _tb, _s);                    \
        (d) = fmaf(-2.0f, _ta, _s);                    \
    } while (0)

// Last stage with folded 1/16 scale: y/16 = fma(-2/16, x, s/16).
#define BF4S(a,b,c,d)                                  \
    do {                                               \
        float _s = (((a)+(b)) + ((c)+(d))) * 0.0625f;  \
        float _ta=(a), _tb=(b), _tc=(c);               \
        (a) = fmaf(-0.125f, (d), _s);                  \
        (b) = fmaf(-0.125f, _tc, _s);                  \
        (c) = fmaf(-0.125f, _tb, _s);                  \
        (d) = fmaf(-0.125f, _ta, _s);                  \
    } while (0)

#define RS 20    // smem row stride in floats (80B, 16B-aligned)
#define SB 336   // smem block stride in floats (336 mod 32 == 16)

__global__ __launch_bounds__(256) void had256_kernel(
    const float* __restrict__ x, float* __restrict__ y)
{
    __shared__ __align__(16) float sm[16 * SB];

    const int tid = threadIdx.x;
    const int h   = tid >> 4;        // hadamard block within CTA [0,16)
    const int j   = tid & 15;        // lane within 16-group [0,16)
    const int sbase = h * SB;

    const size_t blk = ((size_t)blockIdx.x << 12) + ((size_t)h << 8);

    // ---- load 16 consecutive floats: e = 16j + i ----
    const float4* xin = reinterpret_cast<const float4*>(x + blk + ((size_t)j << 4));
    float v[16];
    {
        float4 p;
        p = __ldcs(xin + 0); v[0]=p.x;  v[1]=p.y;  v[2]=p.z;  v[3]=p.w;
        p = __ldcs(xin + 1); v[4]=p.x;  v[5]=p.y;  v[6]=p.z;  v[7]=p.w;
        p = __ldcs(xin + 2); v[8]=p.x;  v[9]=p.y;  v[10]=p.z; v[11]=p.w;
        p = __ldcs(xin + 3); v[12]=p.x; v[13]=p.y; v[14]=p.z; v[15]=p.w;
    }

    // ---- stage d0 (element stride 1 = reg stride 1) ----
    BF4(v[0], v[1], v[2],  v[3]);
    BF4(v[4], v[5], v[6],  v[7]);
    BF4(v[8], v[9], v[10], v[11]);
    BF4(v[12],v[13],v[14], v[15]);
    // ---- stage d1 (element stride 4 = reg stride 4) ----
    BF4(v[0], v[4], v[8],  v[12]);
    BF4(v[1], v[5], v[9],  v[13]);
    BF4(v[2], v[6], v[10], v[14]);
    BF4(v[3], v[7], v[11], v[15]);

    // ---- single transpose: element 16j+i -> row i, col j (scalar STS, CF) ----
    #pragma unroll
    for (int i = 0; i < 16; i++)
        sm[sbase + i * RS + j] = v[i];

    __syncwarp();

    // vector LDS: thread j reads row j -> w[k] = element 16k + j (CF).
    float w[16];
    {
        const float4* rp = reinterpret_cast<const float4*>(sm + sbase + j * RS);
        float4 a;
        a = rp[0]; w[0]=a.x;  w[1]=a.y;  w[2]=a.z;  w[3]=a.w;
        a = rp[1]; w[4]=a.x;  w[5]=a.y;  w[6]=a.z;  w[7]=a.w;
        a = rp[2]; w[8]=a.x;  w[9]=a.y;  w[10]=a.z; w[11]=a.w;
        a = rp[3]; w[12]=a.x; w[13]=a.y; w[14]=a.z; w[15]=a.w;
    }

    // ---- stage d2 (element stride 16 = reg stride 1) ----
    BF4(w[0], w[1], w[2],  w[3]);
    BF4(w[4], w[5], w[6],  w[7]);
    BF4(w[8], w[9], w[10], w[11]);
    BF4(w[12],w[13],w[14], w[15]);
    // ---- stage d3 (element stride 64 = reg stride 4) + 1/16 scale ----
    BF4S(w[0], w[4], w[8],  w[12]);
    BF4S(w[1], w[5], w[9],  w[13]);
    BF4S(w[2], w[6], w[10], w[14]);
    BF4S(w[3], w[7], w[11], w[15]);

    // ---- shuffle-paired STG.64 stores ----
    // Lane pair (2t, 2t+1) holds elements {16k+2t, 16k+2t+1} between them.
    // Even lane stores even-k pairs at blk+32m+j; odd lane stores odd-k
    // pairs at blk+32m+16+(j-1). Per instruction m, each block's 16 lanes
    // write one dense 128B line [128m, 128m+128).
    {
        const int jodd = j & 1;
        float2* yo2 = reinterpret_cast<float2*>(y + blk + (jodd << 4) + (size_t)(j & 14));
        #pragma unroll
        for (int m = 0; m < 8; m++) {
            float pe = __shfl_xor_sync(0xffffffffu, w[2*m],     1);
            float po = __shfl_xor_sync(0xffffffffu, w[2*m + 1], 1);
            float2 q;
            q.x = jodd ? po         : w[2*m];
            q.y = jodd ? w[2*m + 1] : pe;
            __stcs(yo2 + 16*m, q);
        }
    }
}

extern "C" void kernel_launch(void* const* d_in, const int* in_sizes, int n_in,
                              void* d_out, int out_size)
{
    // x = largest input; H is the fixed regular Hadamard matrix, applied
    // analytically by the fast transform (never read).
    int xi = 0;
    long long best = -1;
    for (int i = 0; i < n_in; i++) {
        if ((long long)in_sizes[i] > best) { best = in_sizes[i]; xi = i; }
    }
    const float* x = (const float*)d_in[xi];
    float*       y = (float*)d_out;

    // 4096 elements (16 Hadamard blocks) per CTA.
    int nblocks = out_size >> 12;   // 67108864 -> 16384 CTAs
    had256_kernel<<<nblocks, 256>>>(x, y);
}

// round 9
// speedup vs baseline: 1.0051x; 1.0051x over previous
#include <cuda_runtime.h>
#include <cuda_bf16.h>

// Blockwise 256-point regular Hadamard transform (H = kron(H4 x4) / 16).
// Fast transform, 4 radix-4 stages on independent base-4 digits (stages
// commute -> ONE smem transpose). R8: 2-tile software pipelining per CTA
// to fix DRAM duty cycle (all 8 LDG.128 issued up front; tile B's memory
// latency hides under tile A's compute/transpose/store phase).
//
// Per tile (proven R5 dataflow, 80 L1-wavefronts/warp = structural floor):
//   1. 4x LDG.128: thread (h,j) holds elements e = 16j+i
//   2. butterfly d0,d1 in registers (strides 1,4)
//   3. smem transpose: 16 scalar STS (CF) + 4 LDS.128 (CF), RS=20/SB=336
//   4. thread holds e = 16k+j; butterfly d2,d3 (element strides 16,64 =
//      register strides 1,4); 1/16 scale folded into last stage
//   5. 16 scalar STG.32, each a dense 64B segment per 16-lane group

#define BF4(a,b,c,d)                                   \
    do {                                               \
        float _s = ((a)+(b)) + ((c)+(d));              \
        float _ta=(a), _tb=(b), _tc=(c);               \
        (a) = fmaf(-2.0f, (d), _s);                    \
        (b) = fmaf(-2.0f, _tc, _s);                    \
        (c) = fmaf(-2.0f, _tb, _s);                    \
        (d) = fmaf(-2.0f, _ta, _s);                    \
    } while (0)

// Last stage with folded 1/16 scale: y/16 = fma(-2/16, x, s/16).
#define BF4S(a,b,c,d)                                  \
    do {                                               \
        float _s = (((a)+(b)) + ((c)+(d))) * 0.0625f;  \
        float _ta=(a), _tb=(b), _tc=(c);               \
        (a) = fmaf(-0.125f, (d), _s);                  \
        (b) = fmaf(-0.125f, _tc, _s);                  \
        (c) = fmaf(-0.125f, _tb, _s);                  \
        (d) = fmaf(-0.125f, _ta, _s);                  \
    } while (0)

#define RS 20    // smem row stride in floats (80B, 16B-aligned)
#define SB 336   // smem block stride in floats (336 mod 32 == 16)

#define LOAD16(dst, ptr)                                                   \
    do {                                                                   \
        float4 _p;                                                         \
        _p = __ldcs((ptr) + 0); dst[0]=_p.x;  dst[1]=_p.y;  dst[2]=_p.z;  dst[3]=_p.w;  \
        _p = __ldcs((ptr) + 1); dst[4]=_p.x;  dst[5]=_p.y;  dst[6]=_p.z;  dst[7]=_p.w;  \
        _p = __ldcs((ptr) + 2); dst[8]=_p.x;  dst[9]=_p.y;  dst[10]=_p.z; dst[11]=_p.w; \
        _p = __ldcs((ptr) + 3); dst[12]=_p.x; dst[13]=_p.y; dst[14]=_p.z; dst[15]=_p.w; \
    } while (0)

#define STAGES01(v)                 \
    do {                            \
        BF4(v[0], v[1], v[2],  v[3]);  \
        BF4(v[4], v[5], v[6],  v[7]);  \
        BF4(v[8], v[9], v[10], v[11]); \
        BF4(v[12],v[13],v[14], v[15]); \
        BF4(v[0], v[4], v[8],  v[12]); \
        BF4(v[1], v[5], v[9],  v[13]); \
        BF4(v[2], v[6], v[10], v[14]); \
        BF4(v[3], v[7], v[11], v[15]); \
    } while (0)

#define STAGES23S(w)                 \
    do {                             \
        BF4(w[0], w[1], w[2],  w[3]);   \
        BF4(w[4], w[5], w[6],  w[7]);   \
        BF4(w[8], w[9], w[10], w[11]);  \
        BF4(w[12],w[13],w[14], w[15]);  \
        BF4S(w[0], w[4], w[8],  w[12]); \
        BF4S(w[1], w[5], w[9],  w[13]); \
        BF4S(w[2], w[6], w[10], w[14]); \
        BF4S(w[3], w[7], w[11], w[15]); \
    } while (0)

__global__ __launch_bounds__(256, 5) void had256_kernel(
    const float* __restrict__ x, float* __restrict__ y)
{
    __shared__ __align__(16) float sm[16 * SB];

    const int tid = threadIdx.x;
    const int h   = tid >> 4;        // hadamard block within tile [0,16)
    const int j   = tid & 15;        // lane within 16-group [0,16)
    const int sbase = h * SB;

    // CTA covers 8192 consecutive floats = two 4KB tiles.
    const size_t blkA = ((size_t)blockIdx.x << 13) + ((size_t)h << 8);
    const size_t blkB = blkA + 4096;

    // ---- issue ALL global loads up front (8 LDG.128 in flight) ----
    const float4* xa = reinterpret_cast<const float4*>(x + blkA + ((size_t)j << 4));
    const float4* xb = reinterpret_cast<const float4*>(x + blkB + ((size_t)j << 4));
    float va[16], vb[16];
    LOAD16(va, xa);
    LOAD16(vb, xb);

    // ================= tile A =================
    STAGES01(va);

    #pragma unroll
    for (int i = 0; i < 16; i++)
        sm[sbase + i * RS + j] = va[i];      // va dead after this

    __syncwarp();

    float w[16];
    {
        const float4* rp = reinterpret_cast<const float4*>(sm + sbase + j * RS);
        float4 a;
        a = rp[0]; w[0]=a.x;  w[1]=a.y;  w[2]=a.z;  w[3]=a.w;
        a = rp[1]; w[4]=a.x;  w[5]=a.y;  w[6]=a.z;  w[7]=a.w;
        a = rp[2]; w[8]=a.x;  w[9]=a.y;  w[10]=a.z; w[11]=a.w;
        a = rp[3]; w[12]=a.x; w[13]=a.y; w[14]=a.z; w[15]=a.w;
    }

    STAGES23S(w);

    {
        float* yo = y + blkA + j;
        #pragma unroll
        for (int k = 0; k < 16; k++)
            __stcs(yo + (k << 4), w[k]);
    }

    // ================= tile B =================
    STAGES01(vb);

    __syncwarp();   // all lanes done reading tile A's smem rows

    #pragma unroll
    for (int i = 0; i < 16; i++)
        sm[sbase + i * RS + j] = vb[i];

    __syncwarp();

    {
        const float4* rp = reinterpret_cast<const float4*>(sm + sbase + j * RS);
        float4 a;
        a = rp[0]; w[0]=a.x;  w[1]=a.y;  w[2]=a.z;  w[3]=a.w;
        a = rp[1]; w[4]=a.x;  w[5]=a.y;  w[6]=a.z;  w[7]=a.w;
        a = rp[2]; w[8]=a.x;  w[9]=a.y;  w[10]=a.z; w[11]=a.w;
        a = rp[3]; w[12]=a.x; w[13]=a.y; w[14]=a.z; w[15]=a.w;
    }

    STAGES23S(w);

    {
        float* yo = y + blkB + j;
        #pragma unroll
        for (int k = 0; k < 16; k++)
            __stcs(yo + (k << 4), w[k]);
    }
}

extern "C" void kernel_launch(void* const* d_in, const int* in_sizes, int n_in,
                              void* d_out, int out_size)
{
    // x = largest input; H is the fixed regular Hadamard matrix, applied
    // analytically by the fast transform (never read).
    int xi = 0;
    long long best = -1;
    for (int i = 0; i < n_in; i++) {
        if ((long long)in_sizes[i] > best) { best = in_sizes[i]; xi = i; }
    }
    const float* x = (const float*)d_in[xi];
    float*       y = (float*)d_out;

    // 8192 elements (two 16-block tiles) per CTA.
    int nblocks = out_size >> 13;   // 67108864 -> 8192 CTAs
    had256_kernel<<<nblocks, 256>>>(x, y);
}